// round 1
// baseline (speedup 1.0000x reference)
#include <cuda_runtime.h>
#include <math.h>

// ViewDependentColorMLP fused kernel (fp32 baseline, round 1)
//
// Per block: TILE_M=128 points of one camera.
//   1. Build X^T [64][128] in smem (emb | features | SH bases).
//   2. H0 = relu(X @ W0 + b0)  -> stored transposed in smem  [128][128]
//   3. H1 = relu(H0 @ W1 + b1) -> stored transposed in-place
//   4. out = H1 @ W2 + b2      -> [128][3] to gmem
// 256 threads, 8x8 register microtiles for the 128x128 GEMMs.

#define TILE_M   128
#define TMP      132   // padded row stride for transposed activation tiles
#define NTHREADS 256

__device__ __forceinline__ float frelu(float v) { return v > 0.0f ? v : 0.0f; }

__global__ void __launch_bounds__(NTHREADS, 1)
vdc_mlp_kernel(const float* __restrict__ features,
               const float* __restrict__ dirs,
               const float* __restrict__ embed_table,
               const float* __restrict__ W0, const float* __restrict__ b0,
               const float* __restrict__ W1, const float* __restrict__ b1,
               const float* __restrict__ W2, const float* __restrict__ b2,
               const int*   __restrict__ embed_ids,
               const int*   __restrict__ sh_degree_ptr,
               float* __restrict__ out,
               int N, int C)
{
    extern __shared__ float sm[];
    float* sW0 = sm;                    // [64][128]  = 8192
    float* sW1 = sW0 + 64 * 128;        // [128][128] = 16384
    float* sW2 = sW1 + 128 * 128;       // [128][3]   = 384
    float* sB0 = sW2 + 384;             // 128
    float* sB1 = sB0 + 128;             // 128
    float* sB2 = sB1 + 128;             // 4
    float* sXt = sB2 + 4;               // [64][TMP]
    float* sHt = sXt + 64 * TMP;        // [128][TMP]

    const int tid = threadIdx.x;
    const int tx  = tid & 15;           // 0..15 -> output-col groups
    const int ty  = tid >> 4;           // 0..15 -> output-row groups
    const int c   = blockIdx.y;
    const int n0  = blockIdx.x * TILE_M;

    // ---- stage weights/biases into smem ----
    {
        const float4* s = (const float4*)W0; float4* d = (float4*)sW0;
        #pragma unroll
        for (int v = tid; v < 2048; v += NTHREADS) d[v] = s[v];
    }
    {
        const float4* s = (const float4*)W1; float4* d = (float4*)sW1;
        #pragma unroll
        for (int v = tid; v < 4096; v += NTHREADS) d[v] = s[v];
    }
    for (int v = tid; v < 384; v += NTHREADS) sW2[v] = W2[v];
    if (tid < 128) { sB0[tid] = b0[tid]; sB1[tid] = b1[tid]; }
    if (tid < 3)   sB2[tid] = b2[tid];

    // ---- build X^T tile ----
    // cols 0..15: camera embedding (broadcast per block)
    const int emb_id = embed_ids[c];
    for (int idx = tid; idx < 16 * TILE_M; idx += NTHREADS) {
        int j = idx >> 7;       // 0..15
        int m = idx & 127;      // row within tile
        sXt[j * TMP + m] = embed_table[emb_id * 16 + j];
    }
    // cols 16..47: per-splat features (camera-independent)
    {
        const float4* fs = (const float4*)features + (size_t)n0 * 8;
        for (int v = tid; v < 1024; v += NTHREADS) {
            int m = v >> 3;              // 8 float4 per 32-float row
            int f = (v & 7) * 4;
            float4 val = (n0 + m < N) ? fs[v] : make_float4(0.f, 0.f, 0.f, 0.f);
            float* dst = &sXt[(16 + f) * TMP + m];
            dst[0 * TMP] = val.x;
            dst[1 * TMP] = val.y;
            dst[2 * TMP] = val.z;
            dst[3 * TMP] = val.w;
        }
    }
    // cols 48..63: SH bases of the normalized direction
    if (tid < TILE_M) {
        int n = n0 + tid;
        float dx = 0.f, dy = 0.f, dz = 0.f;
        if (n < N) {
            const float* dp = dirs + ((size_t)c * N + n) * 3;
            dx = dp[0]; dy = dp[1]; dz = dp[2];
        }
        float norm = sqrtf(dx * dx + dy * dy + dz * dz);
        float inv  = 1.0f / fmaxf(norm, 1e-12f);
        float x = dx * inv, y = dy * inv, z = dz * inv;

        float z2     = z * z;
        float fTmp0B = -1.092548430592079f * z;
        float fC1    = x * x - y * y;
        float fS1    = 2.0f * x * y;
        float fTmp0C = -2.285228997322329f * z2 + 0.4570457994644658f;
        float fTmp1B = 1.445305721320277f * z;
        float fC2    = x * fC1 - y * fS1;
        float fS2    = x * fS1 + y * fC1;

        float sh[16];
        sh[0]  = 0.2820947917738781f;
        sh[1]  = -0.48860251190292f * y;
        sh[2]  =  0.48860251190292f * z;
        sh[3]  = -0.48860251190292f * x;
        sh[4]  =  0.5462742152960395f * fS1;
        sh[5]  =  fTmp0B * y;
        sh[6]  =  0.9461746957575601f * z2 - 0.3153915652525201f;
        sh[7]  =  fTmp0B * x;
        sh[8]  =  0.5462742152960395f * fC1;
        sh[9]  = -0.5900435899266435f * fS2;
        sh[10] =  fTmp1B * fS1;
        sh[11] =  fTmp0C * y;
        sh[12] =  z * (1.865881662950577f * z2 - 1.119528997770346f);
        sh[13] =  fTmp0C * x;
        sh[14] =  fTmp1B * fC1;
        sh[15] = -0.5900435899266435f * fC2;

        int deg = sh_degree_ptr ? sh_degree_ptr[0] : 3;
        int nb  = (deg + 1) * (deg + 1);
        #pragma unroll
        for (int j = 0; j < 16; j++)
            sXt[(48 + j) * TMP + tid] = (j < nb) ? sh[j] : 0.0f;
    }
    __syncthreads();

    float acc[8][8];

    // ================= GEMM1: H0 = relu(X @ W0 + b0), K=64 =================
    #pragma unroll
    for (int j = 0; j < 8; j++) {
        int col = (j < 4) ? 4 * tx + j : 60 + 4 * tx + j;  // {4tx+jj, 64+4tx+jj}
        float bv = sB0[col];
        #pragma unroll
        for (int i = 0; i < 8; i++) acc[i][j] = bv;
    }
    #pragma unroll 4
    for (int k = 0; k < 64; k++) {
        const float* ap = &sXt[k * TMP + 8 * ty];
        float4 a0 = *(const float4*)ap;
        float4 a1 = *(const float4*)(ap + 4);
        const float* bp = &sW0[k * 128 + 4 * tx];
        float4 bb0 = *(const float4*)bp;
        float4 bb1 = *(const float4*)(bp + 64);
        float a[8] = {a0.x, a0.y, a0.z, a0.w, a1.x, a1.y, a1.z, a1.w};
        float b[8] = {bb0.x, bb0.y, bb0.z, bb0.w, bb1.x, bb1.y, bb1.z, bb1.w};
        #pragma unroll
        for (int i = 0; i < 8; i++)
            #pragma unroll
            for (int j = 0; j < 8; j++)
                acc[i][j] = fmaf(a[i], b[j], acc[i][j]);
    }
    // store relu(H0) transposed
    #pragma unroll
    for (int j = 0; j < 8; j++) {
        int col = (j < 4) ? 4 * tx + j : 60 + 4 * tx + j;
        float4 s0 = make_float4(frelu(acc[0][j]), frelu(acc[1][j]),
                                frelu(acc[2][j]), frelu(acc[3][j]));
        float4 s1 = make_float4(frelu(acc[4][j]), frelu(acc[5][j]),
                                frelu(acc[6][j]), frelu(acc[7][j]));
        *(float4*)&sHt[col * TMP + 8 * ty]     = s0;
        *(float4*)&sHt[col * TMP + 8 * ty + 4] = s1;
    }
    __syncthreads();

    // ================= GEMM2: H1 = relu(H0 @ W1 + b1), K=128 ================
    #pragma unroll
    for (int j = 0; j < 8; j++) {
        int col = (j < 4) ? 4 * tx + j : 60 + 4 * tx + j;
        float bv = sB1[col];
        #pragma unroll
        for (int i = 0; i < 8; i++) acc[i][j] = bv;
    }
    #pragma unroll 4
    for (int k = 0; k < 128; k++) {
        const float* ap = &sHt[k * TMP + 8 * ty];
        float4 a0 = *(const float4*)ap;
        float4 a1 = *(const float4*)(ap + 4);
        const float* bp = &sW1[k * 128 + 4 * tx];
        float4 bb0 = *(const float4*)bp;
        float4 bb1 = *(const float4*)(bp + 64);
        float a[8] = {a0.x, a0.y, a0.z, a0.w, a1.x, a1.y, a1.z, a1.w};
        float b[8] = {bb0.x, bb0.y, bb0.z, bb0.w, bb1.x, bb1.y, bb1.z, bb1.w};
        #pragma unroll
        for (int i = 0; i < 8; i++)
            #pragma unroll
            for (int j = 0; j < 8; j++)
                acc[i][j] = fmaf(a[i], b[j], acc[i][j]);
    }
    __syncthreads();   // all H0 reads complete before in-place overwrite
    #pragma unroll
    for (int j = 0; j < 8; j++) {
        int col = (j < 4) ? 4 * tx + j : 60 + 4 * tx + j;
        float4 s0 = make_float4(frelu(acc[0][j]), frelu(acc[1][j]),
                                frelu(acc[2][j]), frelu(acc[3][j]));
        float4 s1 = make_float4(frelu(acc[4][j]), frelu(acc[5][j]),
                                frelu(acc[6][j]), frelu(acc[7][j]));
        *(float4*)&sHt[col * TMP + 8 * ty]     = s0;
        *(float4*)&sHt[col * TMP + 8 * ty + 4] = s1;
    }
    __syncthreads();

    // ================= GEMM3: out = H1 @ W2 + b2, N=3 ========================
    if (tid < TILE_M) {
        float o0 = sB2[0], o1 = sB2[1], o2 = sB2[2];
        #pragma unroll 4
        for (int k = 0; k < 128; k++) {
            float v = sHt[k * TMP + tid];
            o0 = fmaf(v, sW2[k * 3 + 0], o0);
            o1 = fmaf(v, sW2[k * 3 + 1], o1);
            o2 = fmaf(v, sW2[k * 3 + 2], o2);
        }
        int n = n0 + tid;
        if (n < N) {
            size_t base = ((size_t)c * N + n) * 3;
            out[base + 0] = o0;
            out[base + 1] = o1;
            out[base + 2] = o2;
        }
    }
}

extern "C" void kernel_launch(void* const* d_in, const int* in_sizes, int n_in,
                              void* d_out, int out_size)
{
    const float* features    = (const float*)d_in[0];
    const float* dirs        = (const float*)d_in[1];
    const float* embed_table = (const float*)d_in[2];
    const float* W0          = (const float*)d_in[3];
    const float* b0          = (const float*)d_in[4];
    const float* W1          = (const float*)d_in[5];
    const float* b1          = (const float*)d_in[6];
    const float* W2          = (const float*)d_in[7];
    const float* b2          = (const float*)d_in[8];
    const int*   embed_ids   = (const int*)d_in[9];
    const int*   shdeg       = (n_in > 10) ? (const int*)d_in[10] : nullptr;

    const int N = in_sizes[0] / 32;          // features is [N, 32]
    const int C = in_sizes[9];               // embed_ids is [C]

    // smem: W0 8192 + W1 16384 + W2 384 + biases 260 + Xt 64*132 + Ht 128*132 floats
    const size_t smem_bytes =
        (size_t)(64 * 128 + 128 * 128 + 384 + 128 + 128 + 4 + 64 * TMP + 128 * TMP)
        * sizeof(float);

    cudaFuncSetAttribute(vdc_mlp_kernel,
                         cudaFuncAttributeMaxDynamicSharedMemorySize,
                         (int)smem_bytes);

    dim3 grid((N + TILE_M - 1) / TILE_M, C);
    vdc_mlp_kernel<<<grid, NTHREADS, smem_bytes>>>(
        features, dirs, embed_table, W0, b0, W1, b1, W2, b2,
        embed_ids, shdeg, (float*)d_out, N, C);
}

// round 5
// speedup vs baseline: 2.8740x; 2.8740x over previous
#include <cuda_runtime.h>
#include <cuda_bf16.h>
#include <stdint.h>

// Persistent split-bf16 HMMA (mma.sync) kernel for sm_103 baseline target.
// Weights live as B-fragments in registers (hi+lo bf16) for the entire kernel.
// Per 128-point tile: build X hi/lo in smem -> GEMM1 (mma.sync, 3-term split)
// -> relu/split -> GEMM2 -> relu -> fp32 H1 in smem -> scalar 128x3 GEMM3.

#define NTHREADS 256

// ---- smem byte offsets ----
#define SM_B0     0         // 128 f32
#define SM_B1     512       // 128 f32
#define SM_W2     1024      // 384 f32
#define SM_B2     2560      // 3 f32
#define SM_PART   2592      // 128*3 f32
#define SM_A1HI   4608      // [128][72] bf16, row stride 144B
#define SM_A1LO   23040
#define SM_A2HI   41472     // [128][136] bf16, row stride 272B
#define SM_A2LO   76288
#define SM_H1     111104    // [128][132] f32, row stride 528B
#define SMEM_TOTAL 178688

#define A1_STRIDE 144
#define A2_STRIDE 272
#define H1_STRIDE 528

__device__ __forceinline__ uint32_t smem_u32(const void* p) {
    uint32_t a;
    asm("{ .reg .u64 t; cvta.to.shared.u64 t, %1; cvt.u32.u64 %0, t; }" : "=r"(a) : "l"(p));
    return a;
}
__device__ __forceinline__ float frelu(float v) { return v > 0.0f ? v : 0.0f; }

// split two floats -> hi bf16x2 (ret) + lo bf16x2 (out)
__device__ __forceinline__ uint32_t split2(float a, float b, uint32_t& lop) {
    __nv_bfloat162 h = __floats2bfloat162_rn(a, b);
    float ra = a - __bfloat162float(h.x);
    float rb = b - __bfloat162float(h.y);
    __nv_bfloat162 l = __floats2bfloat162_rn(ra, rb);
    lop = *reinterpret_cast<uint32_t*>(&l);
    return *reinterpret_cast<uint32_t*>(&h);
}

#define LDSM4(r, addr)                                                      \
    asm volatile("ldmatrix.sync.aligned.m8n8.x4.shared.b16 "                \
                 "{%0,%1,%2,%3}, [%4];"                                     \
                 : "=r"((r)[0]), "=r"((r)[1]), "=r"((r)[2]), "=r"((r)[3])   \
                 : "r"(addr))

#define MMA16816(d, a, b)                                                   \
    asm volatile("mma.sync.aligned.m16n8k16.row.col.f32.bf16.bf16.f32 "     \
                 "{%0,%1,%2,%3}, {%4,%5,%6,%7}, {%8,%9}, {%0,%1,%2,%3};"    \
                 : "+f"((d)[0]), "+f"((d)[1]), "+f"((d)[2]), "+f"((d)[3])   \
                 : "r"((a)[0]), "r"((a)[1]), "r"((a)[2]), "r"((a)[3]),      \
                   "r"((b)[0]), "r"((b)[1]))

__global__ void __launch_bounds__(NTHREADS, 1)
vdc_mlp_hmma(const float* __restrict__ features,
             const float* __restrict__ dirs,
             const float* __restrict__ embed_table,
             const float* __restrict__ W0, const float* __restrict__ b0,
             const float* __restrict__ W1, const float* __restrict__ b1,
             const float* __restrict__ W2, const float* __restrict__ b2,
             const int*   __restrict__ embed_ids,
             const int*   __restrict__ sh_degree_ptr,
             float* __restrict__ out,
             int N, int C)
{
    extern __shared__ char smem[];
    const uint32_t sb = smem_u32(smem);
    const int tid  = threadIdx.x;
    const int lane = tid & 31;
    const int w    = tid >> 5;       // warp 0..7 -> N-slice [16w, 16w+16)
    const int g    = lane >> 2;      // 0..7
    const int tig  = lane & 3;       // 0..3
    const int wbase = w * 16;
    const int p    = tid & 127;      // point row
    const int gg   = tid >> 7;       // 0/1 half

    float* sB0  = (float*)(smem + SM_B0);
    float* sB1  = (float*)(smem + SM_B1);
    float* sW2  = (float*)(smem + SM_W2);
    float* sB2  = (float*)(smem + SM_B2);
    float* part = (float*)(smem + SM_PART);

    // ---- one-time staging: biases + W2 ----
    if (tid < 128) { sB0[tid] = b0[tid]; sB1[tid] = b1[tid]; }
    if (tid < 96) ((float4*)(smem + SM_W2))[tid] = ((const float4*)W2)[tid];
    if (tid == 0) { sB2[0] = b2[0]; sB2[1] = b2[1]; sB2[2] = b2[2]; }

    // ---- one-time: B fragments (hi/lo) into registers ----
    uint32_t b0h[4][2][2], b0l[4][2][2];
    #pragma unroll
    for (int kt = 0; kt < 4; kt++)
        #pragma unroll
        for (int nt = 0; nt < 2; nt++) {
            int n = wbase + nt * 8 + g;
            int k = kt * 16 + tig * 2;
            float v0 = W0[(k)     * 128 + n];
            float v1 = W0[(k + 1) * 128 + n];
            float v2 = W0[(k + 8) * 128 + n];
            float v3 = W0[(k + 9) * 128 + n];
            b0h[kt][nt][0] = split2(v0, v1, b0l[kt][nt][0]);
            b0h[kt][nt][1] = split2(v2, v3, b0l[kt][nt][1]);
        }
    uint32_t b1h[8][2][2], b1l[8][2][2];
    #pragma unroll
    for (int kt = 0; kt < 8; kt++)
        #pragma unroll
        for (int nt = 0; nt < 2; nt++) {
            int n = wbase + nt * 8 + g;
            int k = kt * 16 + tig * 2;
            float v0 = W1[(k)     * 128 + n];
            float v1 = W1[(k + 1) * 128 + n];
            float v2 = W1[(k + 8) * 128 + n];
            float v3 = W1[(k + 9) * 128 + n];
            b1h[kt][nt][0] = split2(v0, v1, b1l[kt][nt][0]);
            b1h[kt][nt][1] = split2(v2, v3, b1l[kt][nt][1]);
        }
    __syncthreads();

    // ldmatrix lane base addresses
    const uint32_t a1base = sb + SM_A1HI + (lane & 15) * A1_STRIDE + (lane >> 4) * 16;
    const uint32_t a2base = sb + SM_A2HI + (lane & 15) * A2_STRIDE + (lane >> 4) * 16;

    const int tilesPerCam = (N + 127) >> 7;
    const int nTiles = tilesPerCam * C;
    const int deg = sh_degree_ptr ? sh_degree_ptr[0] : 3;
    const int nb  = (deg + 1) * (deg + 1);

    for (int t = blockIdx.x; t < nTiles; t += gridDim.x) {
        const int c  = t / tilesPerCam;
        const int m0 = (t - c * tilesPerCam) * 128;

        // ================= build X (A1 hi/lo), rows = points, cols = K =====
        // features -> cols 16..47
        {
            const float4* fs = (const float4*)features + (size_t)m0 * 8;
            #pragma unroll
            for (int v = tid; v < 1024; v += NTHREADS) {
                int m  = v >> 3;
                int fi = v & 7;
                float4 val = (m0 + m < N) ? fs[v] : make_float4(0.f, 0.f, 0.f, 0.f);
                uint32_t l0, l1;
                uint32_t h0 = split2(val.x, val.y, l0);
                uint32_t h1 = split2(val.z, val.w, l1);
                uint32_t off = (uint32_t)(m * A1_STRIDE + 32 + fi * 8);
                *(uint2*)(smem + SM_A1HI + off) = make_uint2(h0, h1);
                *(uint2*)(smem + SM_A1LO + off) = make_uint2(l0, l1);
            }
        }
        if (gg == 1) {
            // camera embedding -> cols 0..15 of row p
            const float* e = embed_table + (size_t)embed_ids[c] * 16;
            #pragma unroll
            for (int j = 0; j < 4; j++) {
                uint32_t l0, l1;
                uint32_t h0 = split2(e[4*j],     e[4*j + 1], l0);
                uint32_t h1 = split2(e[4*j + 2], e[4*j + 3], l1);
                uint32_t off = (uint32_t)(p * A1_STRIDE + j * 8);
                *(uint2*)(smem + SM_A1HI + off) = make_uint2(h0, h1);
                *(uint2*)(smem + SM_A1LO + off) = make_uint2(l0, l1);
            }
        } else {
            // SH bases -> cols 48..63 of row p
            int n = m0 + p;
            float dx = 0.f, dy = 0.f, dz = 0.f;
            if (n < N) {
                const float* dp = dirs + ((size_t)c * N + n) * 3;
                dx = dp[0]; dy = dp[1]; dz = dp[2];
            }
            float norm = sqrtf(dx*dx + dy*dy + dz*dz);
            float inv  = 1.0f / fmaxf(norm, 1e-12f);
            float x = dx*inv, y = dy*inv, z = dz*inv;
            float z2     = z * z;
            float fTmp0B = -1.092548430592079f * z;
            float fC1    = x*x - y*y;
            float fS1    = 2.0f * x * y;
            float fTmp0C = -2.285228997322329f * z2 + 0.4570457994644658f;
            float fTmp1B = 1.445305721320277f * z;
            float fC2    = x*fC1 - y*fS1;
            float fS2    = x*fS1 + y*fC1;
            float sh[16];
            sh[0]  = 0.2820947917738781f;
            sh[1]  = -0.48860251190292f * y;
            sh[2]  =  0.48860251190292f * z;
            sh[3]  = -0.48860251190292f * x;
            sh[4]  =  0.5462742152960395f * fS1;
            sh[5]  =  fTmp0B * y;
            sh[6]  =  0.9461746957575601f * z2 - 0.3153915652525201f;
            sh[7]  =  fTmp0B * x;
            sh[8]  =  0.5462742152960395f * fC1;
            sh[9]  = -0.5900435899266435f * fS2;
            sh[10] =  fTmp1B * fS1;
            sh[11] =  fTmp0C * y;
            sh[12] =  z * (1.865881662950577f * z2 - 1.119528997770346f);
            sh[13] =  fTmp0C * x;
            sh[14] =  fTmp1B * fC1;
            sh[15] = -0.5900435899266435f * fC2;
            #pragma unroll
            for (int j = 0; j < 16; j++) if (j >= nb) sh[j] = 0.0f;
            #pragma unroll
            for (int j = 0; j < 4; j++) {
                uint32_t l0, l1;
                uint32_t h0 = split2(sh[4*j],     sh[4*j + 1], l0);
                uint32_t h1 = split2(sh[4*j + 2], sh[4*j + 3], l1);
                uint32_t off = (uint32_t)(p * A1_STRIDE + 96 + j * 8);
                *(uint2*)(smem + SM_A1HI + off) = make_uint2(h0, h1);
                *(uint2*)(smem + SM_A1LO + off) = make_uint2(l0, l1);
            }
        }
        __syncthreads();

        // ================= GEMM1: H0 = relu(X @ W0 + b0) ====================
        #pragma unroll
        for (int mp = 0; mp < 4; mp++) {
            float d[2][2][4];
            #pragma unroll
            for (int mi = 0; mi < 2; mi++)
                #pragma unroll
                for (int nt = 0; nt < 2; nt++)
                    #pragma unroll
                    for (int q = 0; q < 4; q++) d[mi][nt][q] = 0.0f;

            #pragma unroll
            for (int kt = 0; kt < 4; kt++) {
                uint32_t ah[2][4], al[2][4];
                #pragma unroll
                for (int mi = 0; mi < 2; mi++) {
                    uint32_t addr = a1base + (uint32_t)((mp*32 + mi*16) * A1_STRIDE + kt*32);
                    LDSM4(ah[mi], addr);
                    LDSM4(al[mi], addr + (SM_A1LO - SM_A1HI));
                }
                #pragma unroll
                for (int mi = 0; mi < 2; mi++)
                    #pragma unroll
                    for (int nt = 0; nt < 2; nt++) {
                        MMA16816(d[mi][nt], ah[mi], b0h[kt][nt]);
                        MMA16816(d[mi][nt], ah[mi], b0l[kt][nt]);
                        MMA16816(d[mi][nt], al[mi], b0h[kt][nt]);
                    }
            }
            // epilogue1: relu+bias, split, store A2 hi/lo
            #pragma unroll
            for (int mi = 0; mi < 2; mi++) {
                int r0 = mp*32 + mi*16 + g;
                #pragma unroll
                for (int nt = 0; nt < 2; nt++) {
                    int cc = wbase + nt*8 + tig*2;
                    float f00 = frelu(d[mi][nt][0] + sB0[cc]);
                    float f01 = frelu(d[mi][nt][1] + sB0[cc + 1]);
                    float f10 = frelu(d[mi][nt][2] + sB0[cc]);
                    float f11 = frelu(d[mi][nt][3] + sB0[cc + 1]);
                    uint32_t l0, l1;
                    uint32_t h0 = split2(f00, f01, l0);
                    uint32_t h1 = split2(f10, f11, l1);
                    uint32_t o0 = (uint32_t)(r0 * A2_STRIDE + cc * 2);
                    uint32_t o1 = (uint32_t)((r0 + 8) * A2_STRIDE + cc * 2);
                    *(uint32_t*)(smem + SM_A2HI + o0) = h0;
                    *(uint32_t*)(smem + SM_A2LO + o0) = l0;
                    *(uint32_t*)(smem + SM_A2HI + o1) = h1;
                    *(uint32_t*)(smem + SM_A2LO + o1) = l1;
                }
            }
        }
        __syncthreads();

        // ================= GEMM2: H1 = relu(H0 @ W1 + b1) ===================
        #pragma unroll
        for (int mp = 0; mp < 4; mp++) {
            float d[2][2][4];
            #pragma unroll
            for (int mi = 0; mi < 2; mi++)
                #pragma unroll
                for (int nt = 0; nt < 2; nt++)
                    #pragma unroll
                    for (int q = 0; q < 4; q++) d[mi][nt][q] = 0.0f;

            #pragma unroll
            for (int kt = 0; kt < 8; kt++) {
                uint32_t ah[2][4], al[2][4];
                #pragma unroll
                for (int mi = 0; mi < 2; mi++) {
                    uint32_t addr = a2base + (uint32_t)((mp*32 + mi*16) * A2_STRIDE + kt*32);
                    LDSM4(ah[mi], addr);
                    LDSM4(al[mi], addr + (SM_A2LO - SM_A2HI));
                }
                #pragma unroll
                for (int mi = 0; mi < 2; mi++)
                    #pragma unroll
                    for (int nt = 0; nt < 2; nt++) {
                        MMA16816(d[mi][nt], ah[mi], b1h[kt][nt]);
                        MMA16816(d[mi][nt], ah[mi], b1l[kt][nt]);
                        MMA16816(d[mi][nt], al[mi], b1h[kt][nt]);
                    }
            }
            // epilogue2: relu+bias -> fp32 H1
            #pragma unroll
            for (int mi = 0; mi < 2; mi++) {
                int r0 = mp*32 + mi*16 + g;
                #pragma unroll
                for (int nt = 0; nt < 2; nt++) {
                    int cc = wbase + nt*8 + tig*2;
                    float2 v0 = make_float2(frelu(d[mi][nt][0] + sB1[cc]),
                                            frelu(d[mi][nt][1] + sB1[cc + 1]));
                    float2 v1 = make_float2(frelu(d[mi][nt][2] + sB1[cc]),
                                            frelu(d[mi][nt][3] + sB1[cc + 1]));
                    *(float2*)(smem + SM_H1 + r0 * H1_STRIDE + cc * 4)       = v0;
                    *(float2*)(smem + SM_H1 + (r0 + 8) * H1_STRIDE + cc * 4) = v1;
                }
            }
        }
        __syncthreads();

        // ================= GEMM3: out = H1 @ W2 + b2 ========================
        {
            float o0 = 0.f, o1 = 0.f, o2 = 0.f;
            const float4* hrow = (const float4*)(smem + SM_H1 + p * H1_STRIDE) + gg * 16;
            #pragma unroll
            for (int i = 0; i < 16; i++) {
                float4 hv = hrow[i];
                int k = gg * 64 + i * 4;
                o0 = fmaf(hv.x, sW2[(k+0)*3+0], o0);
                o1 = fmaf(hv.x, sW2[(k+0)*3+1], o1);
                o2 = fmaf(hv.x, sW2[(k+0)*3+2], o2);
                o0 = fmaf(hv.y, sW2[(k+1)*3+0], o0);
                o1 = fmaf(hv.y, sW2[(k+1)*3+1], o1);
                o2 = fmaf(hv.y, sW2[(k+1)*3+2], o2);
                o0 = fmaf(hv.z, sW2[(k+2)*3+0], o0);
                o1 = fmaf(hv.z, sW2[(k+2)*3+1], o1);
                o2 = fmaf(hv.z, sW2[(k+2)*3+2], o2);
                o0 = fmaf(hv.w, sW2[(k+3)*3+0], o0);
                o1 = fmaf(hv.w, sW2[(k+3)*3+1], o1);
                o2 = fmaf(hv.w, sW2[(k+3)*3+2], o2);
            }
            if (gg == 1) {
                part[p*3 + 0] = o0; part[p*3 + 1] = o1; part[p*3 + 2] = o2;
            }
            __syncthreads();
            if (gg == 0) {
                int n = m0 + p;
                if (n < N) {
                    size_t base = ((size_t)c * N + n) * 3;
                    out[base + 0] = o0 + part[p*3 + 0] + sB2[0];
                    out[base + 1] = o1 + part[p*3 + 1] + sB2[1];
                    out[base + 2] = o2 + part[p*3 + 2] + sB2[2];
                }
            }
            __syncthreads();
        }
    }
}

extern "C" void kernel_launch(void* const* d_in, const int* in_sizes, int n_in,
                              void* d_out, int out_size)
{
    const float* features    = (const float*)d_in[0];
    const float* dirs        = (const float*)d_in[1];
    const float* embed_table = (const float*)d_in[2];
    const float* W0          = (const float*)d_in[3];
    const float* b0          = (const float*)d_in[4];
    const float* W1          = (const float*)d_in[5];
    const float* b1          = (const float*)d_in[6];
    const float* W2          = (const float*)d_in[7];
    const float* b2          = (const float*)d_in[8];
    const int*   embed_ids   = (const int*)d_in[9];
    const int*   shdeg       = (n_in > 10) ? (const int*)d_in[10] : nullptr;

    const int N = in_sizes[0] / 32;
    const int C = in_sizes[9];

    int sms = 148;
    cudaDeviceGetAttribute(&sms, cudaDevAttrMultiProcessorCount, 0);

    const int nTiles = ((N + 127) / 128) * C;
    int grid = sms < nTiles ? sms : nTiles;

    cudaFuncSetAttribute(vdc_mlp_hmma,
                         cudaFuncAttributeMaxDynamicSharedMemorySize, SMEM_TOTAL);

    vdc_mlp_hmma<<<grid, NTHREADS, SMEM_TOTAL>>>(
        features, dirs, embed_table, W0, b0, W1, b1, W2, b2,
        embed_ids, shdeg, (float*)d_out, N, C);
}

// round 6
// speedup vs baseline: 3.0446x; 1.0594x over previous
#include <cuda_runtime.h>
#include <cuda_bf16.h>
#include <stdint.h>

// Persistent split-bf16 HMMA kernel, round 6.
//  - camera embedding folded into per-camera fp32 bias (GEMM1 K=48)
//  - 3-term split MMAs reordered for dependency distance 4 + ldmatrix prefetch
//  - GEMM3 in registers (shfl reduce) — no H1 smem buffer, 3 syncs/tile

#define NTHREADS 256

// ---- smem byte offsets ----
#define SM_B1     0          // 128 f32
#define SM_W2     512        // 384 f32
#define SM_B2     2048       // 3 f32
#define SM_BIAS0  2112       // 128 f32 (per-camera fused bias)
#define SM_PART   2624       // 8*128*3 f32 = 12288
#define SM_A1HI   15360      // [128][56] bf16, stride 112B (K=48 + pad)
#define SM_A1LO   29696
#define SM_A2HI   44032      // [128][136] bf16, stride 272B
#define SM_A2LO   78848
#define SMEM_TOTAL 113664

#define A1_STRIDE 112
#define A2_STRIDE 272

__device__ __forceinline__ uint32_t smem_u32(const void* p) {
    uint32_t a;
    asm("{ .reg .u64 t; cvta.to.shared.u64 t, %1; cvt.u32.u64 %0, t; }" : "=r"(a) : "l"(p));
    return a;
}
__device__ __forceinline__ float frelu(float v) { return v > 0.0f ? v : 0.0f; }

__device__ __forceinline__ uint32_t split2(float a, float b, uint32_t& lop) {
    __nv_bfloat162 h = __floats2bfloat162_rn(a, b);
    float ra = a - __bfloat162float(h.x);
    float rb = b - __bfloat162float(h.y);
    __nv_bfloat162 l = __floats2bfloat162_rn(ra, rb);
    lop = *reinterpret_cast<uint32_t*>(&l);
    return *reinterpret_cast<uint32_t*>(&h);
}

#define LDSM4(r, addr)                                                      \
    asm volatile("ldmatrix.sync.aligned.m8n8.x4.shared.b16 "                \
                 "{%0,%1,%2,%3}, [%4];"                                     \
                 : "=r"((r)[0]), "=r"((r)[1]), "=r"((r)[2]), "=r"((r)[3])   \
                 : "r"(addr))

#define MMA16816(d, a, b)                                                   \
    asm volatile("mma.sync.aligned.m16n8k16.row.col.f32.bf16.bf16.f32 "     \
                 "{%0,%1,%2,%3}, {%4,%5,%6,%7}, {%8,%9}, {%0,%1,%2,%3};"    \
                 : "+f"((d)[0]), "+f"((d)[1]), "+f"((d)[2]), "+f"((d)[3])   \
                 : "r"((a)[0]), "r"((a)[1]), "r"((a)[2]), "r"((a)[3]),      \
                   "r"((b)[0]), "r"((b)[1]))

__global__ void __launch_bounds__(NTHREADS, 1)
vdc_mlp_hmma(const float* __restrict__ features,
             const float* __restrict__ dirs,
             const float* __restrict__ embed_table,
             const float* __restrict__ W0, const float* __restrict__ b0,
             const float* __restrict__ W1, const float* __restrict__ b1,
             const float* __restrict__ W2, const float* __restrict__ b2,
             const int*   __restrict__ embed_ids,
             const int*   __restrict__ sh_degree_ptr,
             float* __restrict__ out,
             int N, int C)
{
    extern __shared__ char smem[];
    const uint32_t sb = smem_u32(smem);
    const int tid  = threadIdx.x;
    const int lane = tid & 31;
    const int w    = tid >> 5;        // warp -> N-slice [16w, 16w+16)
    const int g    = lane >> 2;       // 0..7
    const int tig  = lane & 3;        // 0..3
    const int wbase = w * 16;
    const int p    = tid & 127;

    float* sB1   = (float*)(smem + SM_B1);
    float* sW2   = (float*)(smem + SM_W2);
    float* sB2   = (float*)(smem + SM_B2);
    float* sBias = (float*)(smem + SM_BIAS0);
    float* part  = (float*)(smem + SM_PART);

    // ---- one-time staging ----
    if (tid < 128) sB1[tid] = b1[tid];
    if (tid < 96)  ((float4*)(smem + SM_W2))[tid] = ((const float4*)W2)[tid];
    if (tid == 0) { sB2[0] = b2[0]; sB2[1] = b2[1]; sB2[2] = b2[2]; }

    // ---- B fragments in registers: W0 rows 16..63 (K=48), W1 (K=128) ----
    uint32_t b0h[3][2][2], b0l[3][2][2];
    #pragma unroll
    for (int kt = 0; kt < 3; kt++)
        #pragma unroll
        for (int nt = 0; nt < 2; nt++) {
            int n = wbase + nt * 8 + g;
            int k = 16 + kt * 16 + tig * 2;
            float v0 = W0[(k)     * 128 + n];
            float v1 = W0[(k + 1) * 128 + n];
            float v2 = W0[(k + 8) * 128 + n];
            float v3 = W0[(k + 9) * 128 + n];
            b0h[kt][nt][0] = split2(v0, v1, b0l[kt][nt][0]);
            b0h[kt][nt][1] = split2(v2, v3, b0l[kt][nt][1]);
        }
    uint32_t b1h[8][2][2], b1l[8][2][2];
    #pragma unroll
    for (int kt = 0; kt < 8; kt++)
        #pragma unroll
        for (int nt = 0; nt < 2; nt++) {
            int n = wbase + nt * 8 + g;
            int k = kt * 16 + tig * 2;
            float v0 = W1[(k)     * 128 + n];
            float v1 = W1[(k + 1) * 128 + n];
            float v2 = W1[(k + 8) * 128 + n];
            float v3 = W1[(k + 9) * 128 + n];
            b1h[kt][nt][0] = split2(v0, v1, b1l[kt][nt][0]);
            b1h[kt][nt][1] = split2(v2, v3, b1l[kt][nt][1]);
        }

    const uint32_t a1base = sb + SM_A1HI + (lane & 15) * A1_STRIDE + (lane >> 4) * 16;
    const uint32_t a2base = sb + SM_A2HI + (lane & 15) * A2_STRIDE + (lane >> 4) * 16;

    const int tilesPerCam = (N + 127) >> 7;
    const int nTiles = tilesPerCam * C;
    const int deg = sh_degree_ptr ? sh_degree_ptr[0] : 3;
    const int nb  = (deg + 1) * (deg + 1);
    int last_c = -1;

    for (int t = blockIdx.x; t < nTiles; t += gridDim.x) {
        const int c  = t / tilesPerCam;
        const int m0 = (t - c * tilesPerCam) * 128;

        // ---- per-camera fused bias: bias0 = b0 + emb_c @ W0[0:16] ----
        if (c != last_c) {
            last_c = c;
            if (tid < 128) {
                const float* e = embed_table + (size_t)embed_ids[c] * 16;
                float acc = b0[tid];
                #pragma unroll
                for (int j = 0; j < 16; j++)
                    acc = fmaf(e[j], W0[j * 128 + tid], acc);
                sBias[tid] = acc;
            }
        }

        // ---- build X (A1 hi/lo): cols 0..31 features, 32..47 SH ----
        {
            const float4* fs = (const float4*)features + (size_t)m0 * 8;
            #pragma unroll
            for (int v = tid; v < 1024; v += NTHREADS) {
                int m  = v >> 3;
                int fi = v & 7;
                float4 val = (m0 + m < N) ? fs[v] : make_float4(0.f, 0.f, 0.f, 0.f);
                uint32_t l0, l1;
                uint32_t h0 = split2(val.x, val.y, l0);
                uint32_t h1 = split2(val.z, val.w, l1);
                uint32_t off = (uint32_t)(m * A1_STRIDE + fi * 8);
                *(uint2*)(smem + SM_A1HI + off) = make_uint2(h0, h1);
                *(uint2*)(smem + SM_A1LO + off) = make_uint2(l0, l1);
            }
        }
        if (tid < 128) {
            int n = m0 + p;
            float dx = 0.f, dy = 0.f, dz = 0.f;
            if (n < N) {
                const float* dp = dirs + ((size_t)c * N + n) * 3;
                dx = dp[0]; dy = dp[1]; dz = dp[2];
            }
            float norm = sqrtf(dx*dx + dy*dy + dz*dz);
            float inv  = 1.0f / fmaxf(norm, 1e-12f);
            float x = dx*inv, y = dy*inv, z = dz*inv;
            float z2     = z * z;
            float fTmp0B = -1.092548430592079f * z;
            float fC1    = x*x - y*y;
            float fS1    = 2.0f * x * y;
            float fTmp0C = -2.285228997322329f * z2 + 0.4570457994644658f;
            float fTmp1B = 1.445305721320277f * z;
            float fC2    = x*fC1 - y*fS1;
            float fS2    = x*fS1 + y*fC1;
            float sh[16];
            sh[0]  = 0.2820947917738781f;
            sh[1]  = -0.48860251190292f * y;
            sh[2]  =  0.48860251190292f * z;
            sh[3]  = -0.48860251190292f * x;
            sh[4]  =  0.5462742152960395f * fS1;
            sh[5]  =  fTmp0B * y;
            sh[6]  =  0.9461746957575601f * z2 - 0.3153915652525201f;
            sh[7]  =  fTmp0B * x;
            sh[8]  =  0.5462742152960395f * fC1;
            sh[9]  = -0.5900435899266435f * fS2;
            sh[10] =  fTmp1B * fS1;
            sh[11] =  fTmp0C * y;
            sh[12] =  z * (1.865881662950577f * z2 - 1.119528997770346f);
            sh[13] =  fTmp0C * x;
            sh[14] =  fTmp1B * fC1;
            sh[15] = -0.5900435899266435f * fC2;
            #pragma unroll
            for (int j = 0; j < 16; j++) if (j >= nb) sh[j] = 0.0f;
            #pragma unroll
            for (int j = 0; j < 4; j++) {
                uint32_t l0, l1;
                uint32_t h0 = split2(sh[4*j],     sh[4*j + 1], l0);
                uint32_t h1 = split2(sh[4*j + 2], sh[4*j + 3], l1);
                uint32_t off = (uint32_t)(p * A1_STRIDE + 64 + j * 8);
                *(uint2*)(smem + SM_A1HI + off) = make_uint2(h0, h1);
                *(uint2*)(smem + SM_A1LO + off) = make_uint2(l0, l1);
            }
        }
        __syncthreads();

        // ================= GEMM1: H0 = relu(X @ W0[16:] + bias0) ============
        #pragma unroll
        for (int mp = 0; mp < 4; mp++) {
            float d[2][2][4];
            #pragma unroll
            for (int mi = 0; mi < 2; mi++)
                #pragma unroll
                for (int nt = 0; nt < 2; nt++)
                    #pragma unroll
                    for (int q = 0; q < 4; q++) d[mi][nt][q] = 0.0f;

            uint32_t ah[2][2][4], al[2][2][4];
            #pragma unroll
            for (int mi = 0; mi < 2; mi++) {
                uint32_t addr = a1base + (uint32_t)((mp*32 + mi*16) * A1_STRIDE);
                LDSM4(ah[0][mi], addr);
                LDSM4(al[0][mi], addr + (SM_A1LO - SM_A1HI));
            }
            #pragma unroll
            for (int kt = 0; kt < 3; kt++) {
                int cur = kt & 1, nxt = cur ^ 1;
                if (kt < 2) {
                    #pragma unroll
                    for (int mi = 0; mi < 2; mi++) {
                        uint32_t addr = a1base +
                            (uint32_t)((mp*32 + mi*16) * A1_STRIDE + (kt+1)*32);
                        LDSM4(ah[nxt][mi], addr);
                        LDSM4(al[nxt][mi], addr + (SM_A1LO - SM_A1HI));
                    }
                }
                #pragma unroll
                for (int mi = 0; mi < 2; mi++)
                    #pragma unroll
                    for (int nt = 0; nt < 2; nt++)
                        MMA16816(d[mi][nt], ah[cur][mi], b0h[kt][nt]);
                #pragma unroll
                for (int mi = 0; mi < 2; mi++)
                    #pragma unroll
                    for (int nt = 0; nt < 2; nt++)
                        MMA16816(d[mi][nt], ah[cur][mi], b0l[kt][nt]);
                #pragma unroll
                for (int mi = 0; mi < 2; mi++)
                    #pragma unroll
                    for (int nt = 0; nt < 2; nt++)
                        MMA16816(d[mi][nt], al[cur][mi], b0h[kt][nt]);
            }
            // epilogue1: relu + fused bias, split, store A2 hi/lo
            #pragma unroll
            for (int mi = 0; mi < 2; mi++) {
                int r0 = mp*32 + mi*16 + g;
                #pragma unroll
                for (int nt = 0; nt < 2; nt++) {
                    int cc = wbase + nt*8 + tig*2;
                    float f00 = frelu(d[mi][nt][0] + sBias[cc]);
                    float f01 = frelu(d[mi][nt][1] + sBias[cc + 1]);
                    float f10 = frelu(d[mi][nt][2] + sBias[cc]);
                    float f11 = frelu(d[mi][nt][3] + sBias[cc + 1]);
                    uint32_t l0, l1;
                    uint32_t h0 = split2(f00, f01, l0);
                    uint32_t h1 = split2(f10, f11, l1);
                    uint32_t o0 = (uint32_t)(r0 * A2_STRIDE + cc * 2);
                    uint32_t o1 = (uint32_t)((r0 + 8) * A2_STRIDE + cc * 2);
                    *(uint32_t*)(smem + SM_A2HI + o0) = h0;
                    *(uint32_t*)(smem + SM_A2LO + o0) = l0;
                    *(uint32_t*)(smem + SM_A2HI + o1) = h1;
                    *(uint32_t*)(smem + SM_A2LO + o1) = l1;
                }
            }
        }
        __syncthreads();

        // ===== GEMM2 + in-register GEMM3 partials =====
        #pragma unroll
        for (int mp = 0; mp < 4; mp++) {
            float d[2][2][4];
            #pragma unroll
            for (int mi = 0; mi < 2; mi++)
                #pragma unroll
                for (int nt = 0; nt < 2; nt++)
                    #pragma unroll
                    for (int q = 0; q < 4; q++) d[mi][nt][q] = 0.0f;

            uint32_t ah[2][2][4], al[2][2][4];
            #pragma unroll
            for (int mi = 0; mi < 2; mi++) {
                uint32_t addr = a2base + (uint32_t)((mp*32 + mi*16) * A2_STRIDE);
                LDSM4(ah[0][mi], addr);
                LDSM4(al[0][mi], addr + (SM_A2LO - SM_A2HI));
            }
            #pragma unroll
            for (int kt = 0; kt < 8; kt++) {
                int cur = kt & 1, nxt = cur ^ 1;
                if (kt < 7) {
                    #pragma unroll
                    for (int mi = 0; mi < 2; mi++) {
                        uint32_t addr = a2base +
                            (uint32_t)((mp*32 + mi*16) * A2_STRIDE + (kt+1)*32);
                        LDSM4(ah[nxt][mi], addr);
                        LDSM4(al[nxt][mi], addr + (SM_A2LO - SM_A2HI));
                    }
                }
                #pragma unroll
                for (int mi = 0; mi < 2; mi++)
                    #pragma unroll
                    for (int nt = 0; nt < 2; nt++)
                        MMA16816(d[mi][nt], ah[cur][mi], b1h[kt][nt]);
                #pragma unroll
                for (int mi = 0; mi < 2; mi++)
                    #pragma unroll
                    for (int nt = 0; nt < 2; nt++)
                        MMA16816(d[mi][nt], ah[cur][mi], b1l[kt][nt]);
                #pragma unroll
                for (int mi = 0; mi < 2; mi++)
                    #pragma unroll
                    for (int nt = 0; nt < 2; nt++)
                        MMA16816(d[mi][nt], al[cur][mi], b1h[kt][nt]);
            }
            // epilogue2: relu + b1, project onto W2 (in registers)
            float o[4][3];
            #pragma unroll
            for (int r = 0; r < 4; r++) { o[r][0] = o[r][1] = o[r][2] = 0.f; }
            #pragma unroll
            for (int mi = 0; mi < 2; mi++)
                #pragma unroll
                for (int nt = 0; nt < 2; nt++) {
                    int cc = wbase + nt*8 + tig*2;
                    float f00 = frelu(d[mi][nt][0] + sB1[cc]);
                    float f01 = frelu(d[mi][nt][1] + sB1[cc + 1]);
                    float f10 = frelu(d[mi][nt][2] + sB1[cc]);
                    float f11 = frelu(d[mi][nt][3] + sB1[cc + 1]);
                    #pragma unroll
                    for (int q = 0; q < 3; q++) {
                        float w2a = sW2[cc*3 + q], w2b = sW2[(cc+1)*3 + q];
                        o[mi*2+0][q] = fmaf(f00, w2a, fmaf(f01, w2b, o[mi*2+0][q]));
                        o[mi*2+1][q] = fmaf(f10, w2a, fmaf(f11, w2b, o[mi*2+1][q]));
                    }
                }
            // reduce over the 4 tig lanes (same rows, different cols)
            #pragma unroll
            for (int r = 0; r < 4; r++)
                #pragma unroll
                for (int q = 0; q < 3; q++) {
                    float v = o[r][q];
                    v += __shfl_xor_sync(0xffffffffu, v, 1);
                    v += __shfl_xor_sync(0xffffffffu, v, 2);
                    o[r][q] = v;
                }
            if (tig == 0) {
                #pragma unroll
                for (int mi = 0; mi < 2; mi++) {
                    int r0 = mp*32 + mi*16 + g;
                    #pragma unroll
                    for (int q = 0; q < 3; q++) {
                        part[(w*128 + r0) * 3 + q]     = o[mi*2+0][q];
                        part[(w*128 + r0 + 8) * 3 + q] = o[mi*2+1][q];
                    }
                }
            }
        }
        __syncthreads();

        // ---- final cross-warp reduce + store ----
        if (tid < 128) {
            int n = m0 + p;
            if (n < N) {
                float o0 = sB2[0], o1 = sB2[1], o2 = sB2[2];
                #pragma unroll
                for (int ww = 0; ww < 8; ww++) {
                    const float* pp = &part[(ww*128 + p) * 3];
                    o0 += pp[0]; o1 += pp[1]; o2 += pp[2];
                }
                size_t base = ((size_t)c * N + n) * 3;
                out[base + 0] = o0;
                out[base + 1] = o1;
                out[base + 2] = o2;
            }
        }
        // no tail sync needed: A1 (next build) unused since GEMM1; part is
        // rewritten only after two more syncthreads.
    }
}

extern "C" void kernel_launch(void* const* d_in, const int* in_sizes, int n_in,
                              void* d_out, int out_size)
{
    const float* features    = (const float*)d_in[0];
    const float* dirs        = (const float*)d_in[1];
    const float* embed_table = (const float*)d_in[2];
    const float* W0          = (const float*)d_in[3];
    const float* b0          = (const float*)d_in[4];
    const float* W1          = (const float*)d_in[5];
    const float* b1          = (const float*)d_in[6];
    const float* W2          = (const float*)d_in[7];
    const float* b2          = (const float*)d_in[8];
    const int*   embed_ids   = (const int*)d_in[9];
    const int*   shdeg       = (n_in > 10) ? (const int*)d_in[10] : nullptr;

    const int N = in_sizes[0] / 32;
    const int C = in_sizes[9];

    int sms = 148;
    cudaDeviceGetAttribute(&sms, cudaDevAttrMultiProcessorCount, 0);

    const int nTiles = ((N + 127) / 128) * C;
    int grid = sms < nTiles ? sms : nTiles;

    cudaFuncSetAttribute(vdc_mlp_hmma,
                         cudaFuncAttributeMaxDynamicSharedMemorySize, SMEM_TOTAL);

    vdc_mlp_hmma<<<grid, NTHREADS, SMEM_TOTAL>>>(
        features, dirs, embed_table, W0, b0, W1, b1, W2, b2,
        embed_ids, shdeg, (float*)d_out, N, C);
}

// round 8
// speedup vs baseline: 3.2195x; 1.0574x over previous
#include <cuda_runtime.h>
#include <cuda_bf16.h>
#include <stdint.h>

// Round 8: warp-independent split-bf16 HMMA kernel (round-7 design, OOB fixed).
// Weights (transposed, hi/lo bf16) in smem; each warp processes independent
// 16-row chunks end-to-end (build X -> GEMM1 -> GEMM2 -> GEMM3 -> store).
// No __syncthreads in the main loop.

#define NTHREADS 256
#define NWARPS   8

// ---- smem byte offsets ----
#define SM_W0T_HI  0         // [128 n][48 k] bf16, stride 112
#define SM_W0T_LO  14336
#define SM_W1T_HI  28672     // [128 n][128 k] bf16, stride 272
#define SM_W1T_LO  63488
#define SM_A_HI    98304     // 8 warps x [16][48+pad] bf16, stride 112
#define SM_A_LO    112640
#define SM_H_HI    126976    // 8 warps x [16][128+pad] bf16, stride 272
#define SM_H_LO    161792
#define SM_B1      196608    // 128 f32
#define SM_W2      197120    // 384 f32
#define SM_B2      198656    // 3 f32
#define SM_BIASW   198672    // 8 warps x 128 f32 fused bias0
#define SMEM_TOTAL 202768

#define W0T_STRIDE 112
#define W1T_STRIDE 272
#define A_STRIDE   112
#define H_STRIDE   272

__device__ __forceinline__ uint32_t smem_u32(const void* p) {
    uint32_t a;
    asm("{ .reg .u64 t; cvta.to.shared.u64 t, %1; cvt.u32.u64 %0, t; }" : "=r"(a) : "l"(p));
    return a;
}
__device__ __forceinline__ float frelu(float v) { return v > 0.0f ? v : 0.0f; }

__device__ __forceinline__ uint32_t split2(float a, float b, uint32_t& lop) {
    __nv_bfloat162 h = __floats2bfloat162_rn(a, b);
    float ra = a - __bfloat162float(h.x);
    float rb = b - __bfloat162float(h.y);
    __nv_bfloat162 l = __floats2bfloat162_rn(ra, rb);
    lop = *reinterpret_cast<uint32_t*>(&l);
    return *reinterpret_cast<uint32_t*>(&h);
}

#define LDSM4(r, addr)                                                      \
    asm volatile("ldmatrix.sync.aligned.m8n8.x4.shared.b16 "                \
                 "{%0,%1,%2,%3}, [%4];"                                     \
                 : "=r"((r)[0]), "=r"((r)[1]), "=r"((r)[2]), "=r"((r)[3])   \
                 : "r"(addr))

#define MMA16816(d, a, b)                                                   \
    asm volatile("mma.sync.aligned.m16n8k16.row.col.f32.bf16.bf16.f32 "     \
                 "{%0,%1,%2,%3}, {%4,%5,%6,%7}, {%8,%9}, {%0,%1,%2,%3};"    \
                 : "+f"((d)[0]), "+f"((d)[1]), "+f"((d)[2]), "+f"((d)[3])   \
                 : "r"((a)[0]), "r"((a)[1]), "r"((a)[2]), "r"((a)[3]),      \
                   "r"((b)[0]), "r"((b)[1]))

__global__ void __launch_bounds__(NTHREADS, 1)
vdc_mlp_wi(const float* __restrict__ features,
           const float* __restrict__ dirs,
           const float* __restrict__ embed_table,
           const float* __restrict__ W0, const float* __restrict__ b0,
           const float* __restrict__ W1, const float* __restrict__ b1,
           const float* __restrict__ W2, const float* __restrict__ b2,
           const int*   __restrict__ embed_ids,
           const int*   __restrict__ sh_degree_ptr,
           float* __restrict__ out,
           int N, int C)
{
    extern __shared__ char smem[];
    const uint32_t sb = smem_u32(smem);
    const int tid  = threadIdx.x;
    const int lane = tid & 31;
    const int w    = tid >> 5;
    const int g    = lane >> 2;      // 0..7
    const int tig  = lane & 3;       // 0..3

    float* sB1   = (float*)(smem + SM_B1);
    float* sW2   = (float*)(smem + SM_W2);
    float* sB2   = (float*)(smem + SM_B2);
    float* biasw = (float*)(smem + SM_BIASW) + w * 128;

    // ================= one-time weight staging =================
    if (tid < 128) sB1[tid] = b1[tid];
    if (tid < 96)  ((float4*)(smem + SM_W2))[tid] = ((const float4*)W2)[tid];
    if (tid == 0) { sB2[0] = b2[0]; sB2[1] = b2[1]; sB2[2] = b2[2]; }
    // W0t[n][k] = W0[16+k][n], split hi/lo  (k = 0..47)
    for (int idx = tid; idx < 128 * 48; idx += NTHREADS) {
        int n = idx / 48, k = idx - n * 48;
        float v = W0[(16 + k) * 128 + n];
        __nv_bfloat16 h = __float2bfloat16(v);
        float r = v - __bfloat162float(h);
        uint32_t off = (uint32_t)(n * W0T_STRIDE + k * 2);
        *(__nv_bfloat16*)(smem + SM_W0T_HI + off) = h;
        *(__nv_bfloat16*)(smem + SM_W0T_LO + off) = __float2bfloat16(r);
    }
    // W1t[n][k] = W1[k][n]
    for (int idx = tid; idx < 128 * 128; idx += NTHREADS) {
        int n = idx >> 7, k = idx & 127;
        float v = W1[k * 128 + n];
        __nv_bfloat16 h = __float2bfloat16(v);
        float r = v - __bfloat162float(h);
        uint32_t off = (uint32_t)(n * W1T_STRIDE + k * 2);
        *(__nv_bfloat16*)(smem + SM_W1T_HI + off) = h;
        *(__nv_bfloat16*)(smem + SM_W1T_LO + off) = __float2bfloat16(r);
    }
    __syncthreads();

    // ---- per-thread ldmatrix base addresses ----
    const uint32_t aSlab  = sb + SM_A_HI + w * (16 * A_STRIDE);
    const uint32_t hSlab  = sb + SM_H_HI + w * (16 * H_STRIDE);
    const uint32_t a1addr = aSlab + (lane & 15) * A_STRIDE + (lane >> 4) * 16;
    const uint32_t a2addr = hSlab + (lane & 15) * H_STRIDE + (lane >> 4) * 16;
    // B provider rows: lanes 0-7 -> n0-7 k-lo, 8-15 -> n0-7 k-hi,
    //                  16-23 -> n8-15 k-lo, 24-31 -> n8-15 k-hi
    const uint32_t brow = ((lane >> 4) * 8 + (lane & 7));
    const uint32_t bkof = ((lane >> 3) & 1) * 16;
    const uint32_t b0base = sb + SM_W0T_HI + brow * W0T_STRIDE + bkof;
    const uint32_t b1base = sb + SM_W1T_HI + brow * W1T_STRIDE + bkof;

    const int chunksPerCam = (N + 15) >> 4;
    const int totalChunks  = chunksPerCam * C;
    const int deg = sh_degree_ptr ? sh_degree_ptr[0] : 3;
    const int nb  = (deg + 1) * (deg + 1);
    const int gw  = blockIdx.x * NWARPS + w;
    const int gstride = gridDim.x * NWARPS;
    int last_c = -1;

    const float bias2_0 = sB2[0], bias2_1 = sB2[1], bias2_2 = sB2[2];

    for (int ch = gw; ch < totalChunks; ch += gstride) {
        const int c  = ch / chunksPerCam;
        const int m0 = (ch - c * chunksPerCam) * 16;

        // ---- per-warp fused bias0 on camera change ----
        if (c != last_c) {
            last_c = c;
            const float* e = embed_table + (size_t)embed_ids[c] * 16;
            #pragma unroll
            for (int i = 0; i < 4; i++) {
                int col = lane * 4 + i;
                float acc = b0[col];
                #pragma unroll
                for (int j = 0; j < 16; j++)
                    acc = fmaf(e[j], W0[j * 128 + col], acc);
                biasw[col] = acc;
            }
        }

        // ================= build A slab (16 rows x 48 K) =================
        {
            int r = lane >> 1, hh = lane & 1;
            int n = m0 + r;
            const float4* src = (const float4*)(features + (size_t)n * 32) + hh * 4;
            char* aHi = smem + SM_A_HI + w * (16 * A_STRIDE);
            char* aLo = smem + SM_A_LO + w * (16 * A_STRIDE);
            #pragma unroll
            for (int i = 0; i < 4; i++) {
                float4 v = (n < N) ? src[i] : make_float4(0.f, 0.f, 0.f, 0.f);
                uint32_t l0, l1;
                uint32_t h0 = split2(v.x, v.y, l0);
                uint32_t h1 = split2(v.z, v.w, l1);
                uint32_t off = (uint32_t)(r * A_STRIDE + hh * 32 + i * 8);
                *(uint2*)(aHi + off) = make_uint2(h0, h1);
                *(uint2*)(aLo + off) = make_uint2(l0, l1);
            }
            // SH bases: lanes 0..15 each handle one row
            if (lane < 16) {
                int rr = lane;
                int nn = m0 + rr;
                float dx = 0.f, dy = 0.f, dz = 0.f;
                if (nn < N) {
                    const float* dp = dirs + ((size_t)c * N + nn) * 3;
                    dx = dp[0]; dy = dp[1]; dz = dp[2];
                }
                float norm = sqrtf(dx*dx + dy*dy + dz*dz);
                float inv  = 1.0f / fmaxf(norm, 1e-12f);
                float x = dx*inv, y = dy*inv, z = dz*inv;
                float z2     = z * z;
                float fTmp0B = -1.092548430592079f * z;
                float fC1    = x*x - y*y;
                float fS1    = 2.0f * x * y;
                float fTmp0C = -2.285228997322329f * z2 + 0.4570457994644658f;
                float fTmp1B = 1.445305721320277f * z;
                float fC2    = x*fC1 - y*fS1;
                float fS2    = x*fS1 + y*fC1;
                float sh[16];
                sh[0]  = 0.2820947917738781f;
                sh[1]  = -0.48860251190292f * y;
                sh[2]  =  0.48860251190292f * z;
                sh[3]  = -0.48860251190292f * x;
                sh[4]  =  0.5462742152960395f * fS1;
                sh[5]  =  fTmp0B * y;
                sh[6]  =  0.9461746957575601f * z2 - 0.3153915652525201f;
                sh[7]  =  fTmp0B * x;
                sh[8]  =  0.5462742152960395f * fC1;
                sh[9]  = -0.5900435899266435f * fS2;
                sh[10] =  fTmp1B * fS1;
                sh[11] =  fTmp0C * y;
                sh[12] =  z * (1.865881662950577f * z2 - 1.119528997770346f);
                sh[13] =  fTmp0C * x;
                sh[14] =  fTmp1B * fC1;
                sh[15] = -0.5900435899266435f * fC2;
                #pragma unroll
                for (int j = 0; j < 16; j++) if (j >= nb) sh[j] = 0.0f;
                #pragma unroll
                for (int j = 0; j < 4; j++) {
                    uint32_t l0, l1;
                    uint32_t h0 = split2(sh[4*j],     sh[4*j + 1], l0);
                    uint32_t h1 = split2(sh[4*j + 2], sh[4*j + 3], l1);
                    uint32_t off = (uint32_t)(rr * A_STRIDE + 64 + j * 8);
                    *(uint2*)(aHi + off) = make_uint2(h0, h1);
                    *(uint2*)(aLo + off) = make_uint2(l0, l1);
                }
            }
        }
        __syncwarp();

        // ================= GEMM1: 16 x 128, K=48 =================
        float d[16][4];
        #pragma unroll
        for (int i = 0; i < 16; i++)
            #pragma unroll
            for (int q = 0; q < 4; q++) d[i][q] = 0.0f;

        #pragma unroll
        for (int kt = 0; kt < 3; kt++) {
            uint32_t ah[4], al[4];
            LDSM4(ah, a1addr + kt * 32);
            LDSM4(al, a1addr + kt * 32 + (SM_A_LO - SM_A_HI));
            #pragma unroll
            for (int np2 = 0; np2 < 4; np2++) {
                uint32_t bh0[4], bl0[4], bh1[4], bl1[4];
                uint32_t ba = b0base + (uint32_t)(np2 * 32 * W0T_STRIDE + kt * 32);
                LDSM4(bh0, ba);
                LDSM4(bl0, ba + (SM_W0T_LO - SM_W0T_HI));
                LDSM4(bh1, ba + 16 * W0T_STRIDE);
                LDSM4(bl1, ba + 16 * W0T_STRIDE + (SM_W0T_LO - SM_W0T_HI));
                float* d0 = d[np2*4 + 0]; float* d1 = d[np2*4 + 1];
                float* d2 = d[np2*4 + 2]; float* d3 = d[np2*4 + 3];
                MMA16816(d0, ah, bh0);     MMA16816(d1, ah, bh0 + 2);
                MMA16816(d2, ah, bh1);     MMA16816(d3, ah, bh1 + 2);
                MMA16816(d0, ah, bl0);     MMA16816(d1, ah, bl0 + 2);
                MMA16816(d2, ah, bl1);     MMA16816(d3, ah, bl1 + 2);
                MMA16816(d0, al, bh0);     MMA16816(d1, al, bh0 + 2);
                MMA16816(d2, al, bh1);     MMA16816(d3, al, bh1 + 2);
            }
        }

        // ---- epilogue1: relu + fused bias -> H slab (hi/lo) ----
        {
            char* hHi = smem + SM_H_HI + w * (16 * H_STRIDE);
            char* hLo = smem + SM_H_LO + w * (16 * H_STRIDE);
            #pragma unroll
            for (int nt = 0; nt < 16; nt++) {
                int c0 = nt * 8 + tig * 2;
                float bv0 = biasw[c0], bv1 = biasw[c0 + 1];
                float f00 = frelu(d[nt][0] + bv0);
                float f01 = frelu(d[nt][1] + bv1);
                float f10 = frelu(d[nt][2] + bv0);
                float f11 = frelu(d[nt][3] + bv1);
                uint32_t l0, l1;
                uint32_t h0 = split2(f00, f01, l0);
                uint32_t h1 = split2(f10, f11, l1);
                uint32_t o0 = (uint32_t)(g * H_STRIDE + c0 * 2);
                uint32_t o1 = (uint32_t)((g + 8) * H_STRIDE + c0 * 2);
                *(uint32_t*)(hHi + o0) = h0;
                *(uint32_t*)(hLo + o0) = l0;
                *(uint32_t*)(hHi + o1) = h1;
                *(uint32_t*)(hLo + o1) = l1;
            }
        }
        __syncwarp();

        // ================= GEMM2: 16 x 128, K=128 =================
        #pragma unroll
        for (int i = 0; i < 16; i++)
            #pragma unroll
            for (int q = 0; q < 4; q++) d[i][q] = 0.0f;

        #pragma unroll
        for (int kt = 0; kt < 8; kt++) {
            uint32_t ah[4], al[4];
            LDSM4(ah, a2addr + kt * 32);
            LDSM4(al, a2addr + kt * 32 + (SM_H_LO - SM_H_HI));
            #pragma unroll
            for (int np2 = 0; np2 < 4; np2++) {
                uint32_t bh0[4], bl0[4], bh1[4], bl1[4];
                uint32_t ba = b1base + (uint32_t)(np2 * 32 * W1T_STRIDE + kt * 32);
                LDSM4(bh0, ba);
                LDSM4(bl0, ba + (SM_W1T_LO - SM_W1T_HI));
                LDSM4(bh1, ba + 16 * W1T_STRIDE);
                LDSM4(bl1, ba + 16 * W1T_STRIDE + (SM_W1T_LO - SM_W1T_HI));
                float* d0 = d[np2*4 + 0]; float* d1 = d[np2*4 + 1];
                float* d2 = d[np2*4 + 2]; float* d3 = d[np2*4 + 3];
                MMA16816(d0, ah, bh0);     MMA16816(d1, ah, bh0 + 2);
                MMA16816(d2, ah, bh1);     MMA16816(d3, ah, bh1 + 2);
                MMA16816(d0, ah, bl0);     MMA16816(d1, ah, bl0 + 2);
                MMA16816(d2, ah, bl1);     MMA16816(d3, ah, bl1 + 2);
                MMA16816(d0, al, bh0);     MMA16816(d1, al, bh0 + 2);
                MMA16816(d2, al, bh1);     MMA16816(d3, al, bh1 + 2);
            }
        }

        // ---- epilogue2: relu + b1, project onto W2, shfl-reduce, store ----
        {
            float o00 = 0.f, o01 = 0.f, o02 = 0.f;
            float o10 = 0.f, o11 = 0.f, o12 = 0.f;
            #pragma unroll
            for (int nt = 0; nt < 16; nt++) {
                int c0 = nt * 8 + tig * 2;
                float bv0 = sB1[c0], bv1 = sB1[c0 + 1];
                float f00 = frelu(d[nt][0] + bv0);
                float f01 = frelu(d[nt][1] + bv1);
                float f10 = frelu(d[nt][2] + bv0);
                float f11 = frelu(d[nt][3] + bv1);
                float wa0 = sW2[c0*3 + 0], wa1 = sW2[c0*3 + 1], wa2 = sW2[c0*3 + 2];
                float wb0 = sW2[(c0+1)*3 + 0], wb1 = sW2[(c0+1)*3 + 1], wb2 = sW2[(c0+1)*3 + 2];
                o00 = fmaf(f00, wa0, fmaf(f01, wb0, o00));
                o01 = fmaf(f00, wa1, fmaf(f01, wb1, o01));
                o02 = fmaf(f00, wa2, fmaf(f01, wb2, o02));
                o10 = fmaf(f10, wa0, fmaf(f11, wb0, o10));
                o11 = fmaf(f10, wa1, fmaf(f11, wb1, o11));
                o12 = fmaf(f10, wa2, fmaf(f11, wb2, o12));
            }
            o00 += __shfl_xor_sync(0xffffffffu, o00, 1);
            o00 += __shfl_xor_sync(0xffffffffu, o00, 2);
            o01 += __shfl_xor_sync(0xffffffffu, o01, 1);
            o01 += __shfl_xor_sync(0xffffffffu, o01, 2);
            o02 += __shfl_xor_sync(0xffffffffu, o02, 1);
            o02 += __shfl_xor_sync(0xffffffffu, o02, 2);
            o10 += __shfl_xor_sync(0xffffffffu, o10, 1);
            o10 += __shfl_xor_sync(0xffffffffu, o10, 2);
            o11 += __shfl_xor_sync(0xffffffffu, o11, 1);
            o11 += __shfl_xor_sync(0xffffffffu, o11, 2);
            o12 += __shfl_xor_sync(0xffffffffu, o12, 1);
            o12 += __shfl_xor_sync(0xffffffffu, o12, 2);
            if (tig == 0) {
                int n0 = m0 + g;
                if (n0 < N) {
                    size_t base = ((size_t)c * N + n0) * 3;
                    out[base + 0] = o00 + bias2_0;
                    out[base + 1] = o01 + bias2_1;
                    out[base + 2] = o02 + bias2_2;
                }
                int n1 = m0 + g + 8;
                if (n1 < N) {
                    size_t base = ((size_t)c * N + n1) * 3;
                    out[base + 0] = o10 + bias2_0;
                    out[base + 1] = o11 + bias2_1;
                    out[base + 2] = o12 + bias2_2;
                }
            }
        }
        __syncwarp();
    }
}

extern "C" void kernel_launch(void* const* d_in, const int* in_sizes, int n_in,
                              void* d_out, int out_size)
{
    const float* features    = (const float*)d_in[0];
    const float* dirs        = (const float*)d_in[1];
    const float* embed_table = (const float*)d_in[2];
    const float* W0          = (const float*)d_in[3];
    const float* b0          = (const float*)d_in[4];
    const float* W1          = (const float*)d_in[5];
    const float* b1          = (const float*)d_in[6];
    const float* W2          = (const float*)d_in[7];
    const float* b2          = (const float*)d_in[8];
    const int*   embed_ids   = (const int*)d_in[9];
    const int*   shdeg       = (n_in > 10) ? (const int*)d_in[10] : nullptr;

    const int N = in_sizes[0] / 32;
    const int C = in_sizes[9];

    int sms = 148;
    cudaDeviceGetAttribute(&sms, cudaDevAttrMultiProcessorCount, 0);

    const int chunks = ((N + 15) / 16) * C;
    int grid = sms;
    int maxBlocks = (chunks + NWARPS - 1) / NWARPS;
    if (grid > maxBlocks) grid = maxBlocks;

    cudaFuncSetAttribute(vdc_mlp_wi,
                         cudaFuncAttributeMaxDynamicSharedMemorySize, SMEM_TOTAL);

    vdc_mlp_wi<<<grid, NTHREADS, SMEM_TOTAL>>>(
        features, dirs, embed_table, W0, b0, W1, b1, W2, b2,
        embed_ids, shdeg, (float*)d_out, N, C);
}